// round 16
// baseline (speedup 1.0000x reference)
#include <cuda_runtime.h>
#include <cuda_bf16.h>
#include <cuda_fp16.h>
#include <cstdint>
#include <cstddef>

// Problem dims
#define BB 256
#define TT 1024
#define II 128
#define CC 256
#define GG 512   // 2C
#define OO 10

// Scratch (static device globals -- allocation-free kernel_launch)
__device__ __half g_xz[(size_t)TT * BB * GG];  // [t][b][g]  (256 MB, fp16)
__device__ float g_h[BB * CC];                 // final hidden state

__device__ __forceinline__ float tanh_fast(float x) {
    float r;
    asm("tanh.approx.f32 %0, %1;" : "=f"(r) : "f"(x));   // MUFU.TANH, sm_75+
    return r;
}

// ---- shared mma.sync helpers (sm_80-class PTX; valid on compute_103) ----
__device__ __forceinline__ void ldsm_x4(uint32_t (&r)[4], uint32_t addr) {
    asm volatile("ldmatrix.sync.aligned.m8n8.x4.shared.b16 {%0,%1,%2,%3}, [%4];"
                 : "=r"(r[0]), "=r"(r[1]), "=r"(r[2]), "=r"(r[3]) : "r"(addr));
}
__device__ __forceinline__ void ldsm_x2t(uint32_t& r0, uint32_t& r1, uint32_t addr) {
    asm volatile("ldmatrix.sync.aligned.m8n8.x2.trans.shared.b16 {%0,%1}, [%2];"
                 : "=r"(r0), "=r"(r1) : "r"(addr));
}
__device__ __forceinline__ void mma_bf16(float (&d)[4], const uint32_t (&a)[4],
                                         uint32_t b0, uint32_t b1) {
    asm volatile("mma.sync.aligned.m16n8k16.row.col.f32.bf16.bf16.f32 "
                 "{%0,%1,%2,%3}, {%4,%5,%6,%7}, {%8,%9}, {%0,%1,%2,%3};"
                 : "+f"(d[0]), "+f"(d[1]), "+f"(d[2]), "+f"(d[3])
                 : "r"(a[0]), "r"(a[1]), "r"(a[2]), "r"(a[3]), "r"(b0), "r"(b1));
}
__device__ __forceinline__ void mma_f16(float (&d)[4], const uint32_t (&a)[4],
                                        uint32_t b0, uint32_t b1) {
    asm volatile("mma.sync.aligned.m16n8k16.row.col.f32.f16.f16.f32 "
                 "{%0,%1,%2,%3}, {%4,%5,%6,%7}, {%8,%9}, {%0,%1,%2,%3};"
                 : "+f"(d[0]), "+f"(d[1]), "+f"(d[2]), "+f"(d[3])
                 : "r"(a[0]), "r"(a[1]), "r"(a[2]), "r"(a[3]), "r"(b0), "r"(b1));
}
__device__ __forceinline__ uint32_t hpack(__half a, __half b) {
    return (uint32_t)__half_as_ushort(a) | ((uint32_t)__half_as_ushort(b) << 16);
}
__device__ __forceinline__ void bfsplit(float v, __nv_bfloat16& h, __nv_bfloat16& l) {
    h = __float2bfloat16_rn(v);
    l = __float2bfloat16_rn(v - __bfloat162float(h));
}

// ============================================================================
// Phase 1: xz = x @ kernel + bias, EXACT bf16 3-pass (proven R14 structure),
// now storing xz as fp16 (halves the dominant DRAM write traffic).
// ============================================================================
#define XG_THREADS 256
#define XG_AXH 0
#define XG_AXL 18432
#define XG_BWH 36864
#define XG_BWL 54272
#define XG_SMEM 71680

__global__ void __launch_bounds__(XG_THREADS, 2)
xz_gemm_tc(const float* __restrict__ x, const float* __restrict__ wk,
           const float* __restrict__ bias) {
    extern __shared__ __align__(1024) unsigned char smem[];
    const uint32_t sbase = (uint32_t)__cvta_generic_to_shared(smem);

    const int tid  = threadIdx.x;
    const int w    = tid >> 5;
    const int lane = tid & 31;
    const int warp_m = w >> 1;
    const int warp_n = w & 1;
    const int m0 = blockIdx.y * 128;
    const int n0 = blockIdx.x * 128;

    const int li = lane & 7, lj = lane >> 3;
    const uint32_t aAddrH = sbase + XG_AXH +
        (uint32_t)((warp_m * 32 + li + (lj & 1) * 8) * 144 + ((lj >> 1) * 8) * 2);
    const uint32_t aAddrL = aAddrH + (XG_AXL - XG_AXH);
    const uint32_t bAddrH = sbase + XG_BWH +
        (uint32_t)((lane & 15) * 272 + (warp_n * 64) * 2);
    const uint32_t bAddrL = bAddrH + (XG_BWL - XG_BWH);

    float d[2][8][4];
    #pragma unroll
    for (int mt = 0; mt < 2; mt++)
        #pragma unroll
        for (int nt = 0; nt < 8; nt++)
            #pragma unroll
            for (int i = 0; i < 4; i++) d[mt][nt][i] = 0.0f;

    #pragma unroll
    for (int kc = 0; kc < 2; kc++) {
        #pragma unroll
        for (int i = 0; i < 8; i++) {
            int idx = tid + i * 256;
            int r = idx >> 4, c4 = (idx & 15) * 4;
            float4 v = *(const float4*)(x + (size_t)(m0 + r) * II + kc * 64 + c4);
            __nv_bfloat16 h0, l0, h1, l1, h2, l2, h3, l3;
            bfsplit(v.x, h0, l0); bfsplit(v.y, h1, l1);
            bfsplit(v.z, h2, l2); bfsplit(v.w, h3, l3);
            unsigned char* ph = smem + XG_AXH + r * 144 + c4 * 2;
            unsigned char* pl = smem + XG_AXL + r * 144 + c4 * 2;
            *(__nv_bfloat162*)(ph)     = __halves2bfloat162(h0, h1);
            *(__nv_bfloat162*)(ph + 4) = __halves2bfloat162(h2, h3);
            *(__nv_bfloat162*)(pl)     = __halves2bfloat162(l0, l1);
            *(__nv_bfloat162*)(pl + 4) = __halves2bfloat162(l2, l3);
        }
        #pragma unroll
        for (int i = 0; i < 8; i++) {
            int idx = tid + i * 256;
            int kk = idx >> 5, c4 = (idx & 31) * 4;
            float4 v = *(const float4*)(wk + (size_t)(kc * 64 + kk) * GG + n0 + c4);
            __nv_bfloat16 h0, l0, h1, l1, h2, l2, h3, l3;
            bfsplit(v.x, h0, l0); bfsplit(v.y, h1, l1);
            bfsplit(v.z, h2, l2); bfsplit(v.w, h3, l3);
            unsigned char* ph = smem + XG_BWH + kk * 272 + c4 * 2;
            unsigned char* pl = smem + XG_BWL + kk * 272 + c4 * 2;
            *(__nv_bfloat162*)(ph)     = __halves2bfloat162(h0, h1);
            *(__nv_bfloat162*)(ph + 4) = __halves2bfloat162(h2, h3);
            *(__nv_bfloat162*)(pl)     = __halves2bfloat162(l0, l1);
            *(__nv_bfloat162*)(pl + 4) = __halves2bfloat162(l2, l3);
        }
        __syncthreads();

        #pragma unroll
        for (int ks = 0; ks < 4; ks++) {
            uint32_t ah[2][4], al[2][4];
            #pragma unroll
            for (int mt = 0; mt < 2; mt++) {
                ldsm_x4(ah[mt], aAddrH + (uint32_t)(mt * 2304 + ks * 32));
                ldsm_x4(al[mt], aAddrL + (uint32_t)(mt * 2304 + ks * 32));
            }
            #pragma unroll
            for (int nt = 0; nt < 8; nt++) {
                uint32_t bh0, bh1, bl0, bl1;
                ldsm_x2t(bh0, bh1, bAddrH + (uint32_t)(ks * 4352 + nt * 16));
                ldsm_x2t(bl0, bl1, bAddrL + (uint32_t)(ks * 4352 + nt * 16));
                #pragma unroll
                for (int mt = 0; mt < 2; mt++) {
                    mma_bf16(d[mt][nt], ah[mt], bh0, bh1);
                    mma_bf16(d[mt][nt], ah[mt], bl0, bl1);
                    mma_bf16(d[mt][nt], al[mt], bh0, bh1);
                }
            }
        }
        __syncthreads();
    }

    const int q = lane >> 2, tig = lane & 3;
    #pragma unroll
    for (int nt = 0; nt < 8; nt++) {
        const int col = n0 + warp_n * 64 + nt * 8 + 2 * tig;
        float2 bz = *(const float2*)&bias[col];
        #pragma unroll
        for (int mt = 0; mt < 2; mt++) {
            int mrow = m0 + warp_m * 32 + mt * 16 + q;
            #pragma unroll
            for (int half = 0; half < 2; half++) {
                int m = mrow + half * 8;
                int b = m >> 10, t = m & (TT - 1);
                __half2 hv = __halves2half2(
                    __float2half_rn(d[mt][nt][2 * half + 0] + bz.x),
                    __float2half_rn(d[mt][nt][2 * half + 1] + bz.y));
                *(__half2*)&g_xz[((size_t)t * BB + b) * GG + col] = hv;
            }
        }
    }
}

// ============================================================================
// Phase 2: recurrence. EXACT W (fp16 hi + unscaled fp16 lo, both in registers,
// shared fp32 accumulator chains), fp16 h, fp16 xz, tanh.approx gates,
// st.async + mbarrier complete_tx sync, and — the headline fix — B stage row
// stride 272B (was 256B: all 16 ldmatrix lanes hit one bank group, ~16-way
// LDSM conflict; 272B = 2-way max, same pattern as the GEMM's proven B tile).
// ============================================================================
#define NN 4
#define SC_THREADS 256
#define SC_BSTR  272                          // B stage row stride (bytes)
#define SC_STAGE (256 * SC_BSTR)              // 69632 B
#define SC_SMEM_BYTES (2 * SC_STAGE + 16)     // + 2 mbarriers

__global__ void __launch_bounds__(SC_THREADS, 1) __cluster_dims__(NN, 1, 1)
janet_scan_mma(const float* __restrict__ rk /* [C][2C] */) {
    extern __shared__ __align__(1024) unsigned char smem[];
    const uint32_t sbase = (uint32_t)__cvta_generic_to_shared(smem);
    const uint32_t mb_base = sbase + 2 * SC_STAGE;      // mb[0], mb[1] (8B each)

    const int tid  = threadIdx.x;
    const int w    = tid >> 5;
    const int lane = tid & 31;
    const int q    = lane >> 2;
    const int cq   = lane & 3;
    const int e    = q & 1;

    const unsigned rank = blockIdx.x & (NN - 1);
    const unsigned tile = blockIdx.x >> 2;

    // ---- zero both h stages (h0 = 0)
    for (int i = tid; i < 2 * SC_STAGE / 4; i += SC_THREADS)
        *(uint32_t*)(smem + 4 * i) = 0u;

    // ---- W fragments into registers: fp16 hi + UNSCALED fp16 lo (exact split;
    //      residual <= 2^-11|v| sits in fp16 normals/denormals, shares the
    //      fp32 accumulator chains -> no epilogue rescale)
    uint32_t a_hi[16][4], a_lo[16][4];
    #pragma unroll
    for (int ks = 0; ks < 16; ks++) {
        #pragma unroll
        for (int r = 0; r < 4; r++) {
            int m  = w * 16 + q + (r & 1) * 8;
            int k0 = ks * 16 + 2 * cq + (r >> 1) * 8;
            int col = (m & 1) ? (CC + 64 * (int)rank + (m >> 1))
                              : (64 * (int)rank + (m >> 1));
            float v0 = __ldg(rk + (size_t)k0 * GG + col);
            float v1 = __ldg(rk + (size_t)(k0 + 1) * GG + col);
            __half h0 = __float2half_rn(v0);
            __half h1 = __float2half_rn(v1);
            __half l0 = __float2half_rn(v0 - __half2float(h0));
            __half l1 = __float2half_rn(v1 - __half2float(h1));
            a_hi[ks][r] = hpack(h0, h1);
            a_lo[ks][r] = hpack(l0, l1);
        }
    }

    // ---- mbarrier init + pre-arm both stages (count 1; expect 4096 B)
    if (tid == 0) {
        asm volatile("mbarrier.init.shared.b64 [%0], 1;" :: "r"(mb_base) : "memory");
        asm volatile("mbarrier.init.shared.b64 [%0], 1;" :: "r"(mb_base + 8) : "memory");
        asm volatile("mbarrier.arrive.expect_tx.shared.b64 _, [%0], %1;"
                     :: "r"(mb_base), "r"(4096u) : "memory");
        asm volatile("mbarrier.arrive.expect_tx.shared.b64 _, [%0], %1;"
                     :: "r"(mb_base + 8), "r"(4096u) : "memory");
    }
    __syncthreads();
    asm volatile("barrier.cluster.arrive.aligned;" ::: "memory");
    asm volatile("barrier.cluster.wait.aligned;"   ::: "memory");

    // ---- peer addresses (B stages + mbarriers)
    uint32_t peerB[NN], peerMB[NN];
    #pragma unroll
    for (int p = 0; p < NN; p++) {
        asm volatile("mapa.shared::cluster.u32 %0, %1, %2;"
                     : "=r"(peerB[p]) : "r"(sbase), "r"(p));
        asm volatile("mapa.shared::cluster.u32 %0, %1, %2;"
                     : "=r"(peerMB[p]) : "r"(mb_base), "r"(p));
    }

    const uint32_t b_row = (uint32_t)((lane & 15) * SC_BSTR);
    const int n0    = 2 * cq;
    const int cell0 = 64 * (int)rank + w * 8 + (q >> 1);

    const __half* xzp = g_xz + (e ? CC : 0) + (size_t)(tile * 8 + n0) * GG + cell0;
    float pf[2][2];
    pf[0][0] = __half2float(__ldg(xzp));
    pf[0][1] = __half2float(__ldg(xzp + GG));
    pf[1][0] = __half2float(__ldg(xzp + 4));
    pf[1][1] = __half2float(__ldg(xzp + GG + 4));

    float cst[2][2] = {{0.f, 0.f}, {0.f, 0.f}};
    uint32_t p0 = 0, p1 = 0;    // mbarrier phase parities

    for (int t = 0; t < TT; t++) {
        const int cur = t & 1;

        // ---- wait for this stage's h (skip t=0: stage 0 pre-zeroed locally)
        if (t > 0) {
            const uint32_t mb = mb_base + (uint32_t)cur * 8u;
            const uint32_t par = cur ? p1 : p0;
            uint32_t done;
            asm volatile("{\n\t.reg .pred p;\n\t"
                         "mbarrier.try_wait.parity.acquire.cta.shared::cta.b64 p, [%1], %2;\n\t"
                         "selp.b32 %0, 1, 0, p;\n\t}"
                         : "=r"(done) : "r"(mb), "r"(par) : "memory");
            if (!done) {
                asm volatile("{\n\t.reg .pred P1;\n\t"
                             "WL_%=:\n\t"
                             "mbarrier.try_wait.parity.acquire.cta.shared::cta.b64 P1, [%0], %1, 0x989680;\n\t"
                             "@P1 bra.uni WD_%=;\n\t"
                             "bra.uni WL_%=;\n\t"
                             "WD_%=:\n\t}"
                             :: "r"(mb), "r"(par) : "memory");
            }
            if (tid == 0) {   // re-arm for use at t+2
                asm volatile("mbarrier.arrive.expect_tx.shared.b64 _, [%0], %1;"
                             :: "r"(mb), "r"(4096u) : "memory");
            }
            if (cur) p1 ^= 1; else p0 ^= 1;
        }

        const uint32_t bst = sbase + (uint32_t)cur * SC_STAGE;

        // ---- 2-pass exact-W MMA, 4 shared accumulator chains
        float d[4][4];
        #pragma unroll
        for (int ch = 0; ch < 4; ch++)
            #pragma unroll
            for (int i = 0; i < 4; i++) d[ch][i] = 0.0f;

        #pragma unroll
        for (int ks = 0; ks < 16; ks++) {
            uint32_t b0, b1;
            ldsm_x2t(b0, b1, bst + (uint32_t)(ks * 16 * SC_BSTR) + b_row);
            mma_f16(d[ks & 3], a_hi[ks], b0, b1);
            mma_f16(d[ks & 3], a_lo[ks], b0, b1);
        }

        // z (own kind) = chain sum + xz
        float zo[2][2];
        #pragma unroll
        for (int rr = 0; rr < 2; rr++)
            #pragma unroll
            for (int col = 0; col < 2; col++) {
                int i = rr * 2 + col;
                zo[rr][col] = (d[0][i] + d[1][i]) + (d[2][i] + d[3][i]) + pf[rr][col];
            }

        // pair f/g via quad exchange (q ^ 1)
        float zx[2][2];
        #pragma unroll
        for (int rr = 0; rr < 2; rr++)
            #pragma unroll
            for (int col = 0; col < 2; col++)
                zx[rr][col] = __shfl_xor_sync(0xffffffffu, zo[rr][col], 4);

        const int nxt = cur ^ 1;
        #pragma unroll
        for (int rr = 0; rr < 2; rr++) {
            __half v01[2];
            #pragma unroll
            for (int col = 0; col < 2; col++) {
                float zf = e ? zx[rr][col] : zo[rr][col];
                float zg = e ? zo[rr][col] : zx[rr][col];
                float f = fmaf(0.5f, tanh_fast(0.5f * zf), 0.5f);   // sigmoid
                float g = tanh_fast(zg);
                float c = f * cst[rr][col] + (1.0f - f) * g;
                cst[rr][col] = c;
                v01[col] = __float2half_rn(c);
            }
            if (e == 0) {   // even quads store h, carrying complete_tx to peers
                uint32_t pk = hpack(v01[0], v01[1]);
                uint32_t off = (uint32_t)nxt * SC_STAGE +
                               (uint32_t)((cell0 + rr * 4) * SC_BSTR + n0 * 2);
                #pragma unroll
                for (int p = 0; p < NN; p++) {
                    asm volatile(
                        "st.async.shared::cluster.mbarrier::complete_tx::bytes.b32 [%0], %1, [%2];"
                        :: "r"(peerB[p] + off), "r"(pk), "r"(peerMB[p] + (uint32_t)nxt * 8u)
                        : "memory");
                }
            }
        }

        // ---- prefetch next step's xz
        if (t + 1 < TT) xzp += (size_t)BB * GG;
        pf[0][0] = __half2float(__ldg(xzp));
        pf[0][1] = __half2float(__ldg(xzp + GG));
        pf[1][0] = __half2float(__ldg(xzp + 4));
        pf[1][1] = __half2float(__ldg(xzp + GG + 4));
    }

    // ---- final h (even quads hold canonical values)
    if (e == 0) {
        #pragma unroll
        for (int rr = 0; rr < 2; rr++)
            #pragma unroll
            for (int col = 0; col < 2; col++)
                g_h[((int)tile * 8 + n0 + col) * CC + cell0 + rr * 4] = cst[rr][col];
    }

    // no CTA may exit while peers' st.async targeting its SMEM is in flight
    asm volatile("barrier.cluster.arrive.aligned;" ::: "memory");
    asm volatile("barrier.cluster.wait.aligned;"   ::: "memory");
}

// ============================================================================
// Phase 3: out = h_final @ dense_w + dense_b   (256x256 @ 256x10)
// ============================================================================
__global__ void __launch_bounds__(32) dense_kernel(const float* __restrict__ dw,
                                                   const float* __restrict__ db,
                                                   float* __restrict__ out) {
    int b = blockIdx.x;
    int o = threadIdx.x;
    if (o < OO) {
        float acc = 0.0f;
        #pragma unroll 8
        for (int c = 0; c < CC; c++) {
            acc += g_h[b * CC + c] * dw[c * OO + o];
        }
        out[b * OO + o] = acc + db[o];
    }
}

// ============================================================================
extern "C" void kernel_launch(void* const* d_in, const int* in_sizes, int n_in,
                              void* d_out, int out_size) {
    const float* x  = (const float*)d_in[0];
    const float* wk = (const float*)d_in[1];
    const float* rk = (const float*)d_in[2];
    const float* rb = (const float*)d_in[3];
    const float* dw = (const float*)d_in[4];
    const float* db = (const float*)d_in[5];
    float* out = (float*)d_out;

    // Phase 1: input projection GEMM on tensor cores (exact bf16 3-pass, fp16 out)
    cudaFuncSetAttribute(xz_gemm_tc, cudaFuncAttributeMaxDynamicSharedMemorySize, XG_SMEM);
    xz_gemm_tc<<<dim3(GG / 128, (BB * TT) / 128), XG_THREADS, XG_SMEM>>>(x, wk, rb);

    // Phase 2: exact-W fp16 mma.sync recurrence, conflict-free B stage
    cudaFuncSetAttribute(janet_scan_mma, cudaFuncAttributeMaxDynamicSharedMemorySize, SC_SMEM_BYTES);
    janet_scan_mma<<<32 * NN, SC_THREADS, SC_SMEM_BYTES>>>(rk);

    // Phase 3: final dense
    dense_kernel<<<BB, 32>>>(dw, db, out);
}